// round 4
// baseline (speedup 1.0000x reference)
#include <cuda_runtime.h>
#include <stdint.h>

// Problem constants (fixed by the reference)
#define BATCH 128
#define NN    512
#define NBINS 100
#define WPR   (NN / 32)   // 16 words per bitset row
#define RSTR  20          // padded row stride in words (80B, 16B-aligned)

// Scratch (allocation-free: __device__ globals)
__device__ float    g_histf[2][BATCH][NBINS];   // histograms (exact small ints)
__device__ float    g_acc[3];                   // Kxx, Kyy, Kxy sums
__device__ unsigned g_done = 0;                 // mmd completion ticket

// ---------------------------------------------------------------------------
// Kernel 1 (FUSED pack + cluster): one block per graph.
//  A: stream 1MB fp32 adjacency (float4 LDG.128), shfl-tree pack to smem bitset.
//  B: per-node triangle count, intersections via LDS.128 (rows stride 20 words:
//     bank-quad (5j+q) mod 8 bijective in j mod 8 -> near-conflict-free).
//  C: block-local histogram -> direct global store (block owns its slot).
// ---------------------------------------------------------------------------
__global__ void __launch_bounds__(512) cluster_kernel(
        const float* __restrict__ a1, const float* __restrict__ a2) {
    int sb = blockIdx.x;          // 0..255
    int s  = sb >> 7;
    int b  = sb & (BATCH - 1);

    __shared__ uint4 rows4[NN][RSTR / 4];    // 512*80 = 40960 B, 16B aligned
    __shared__ int   shist[NBINS];
    uint32_t* rowsW = reinterpret_cast<uint32_t*>(rows4);

    int wid  = threadIdx.x >> 5;
    int lane = threadIdx.x & 31;

    if (sb == 0 && threadIdx.x < 3) g_acc[threadIdx.x] = 0.0f;  // stream-ordered

    // ---- Phase A: pack directly from global floats ----
    const float4* __restrict__ src =
        reinterpret_cast<const float4*>((s ? a2 : a1) + (size_t)b * NN * NN);

    for (int r = wid; r < NN; r += 16) {           // 32 rows per warp
        const float4* p = src + r * (NN / 4);      // 128 float4 per row
#pragma unroll
        for (int q = 0; q < 4; ++q) {
            float4 v = p[q * 32 + lane];           // contiguous per-warp
            uint32_t nib = (uint32_t)(v.x != 0.0f)
                         | ((uint32_t)(v.y != 0.0f) << 1)
                         | ((uint32_t)(v.z != 0.0f) << 2)
                         | ((uint32_t)(v.w != 0.0f) << 3);
            uint32_t t;
            t = __shfl_xor_sync(0xffffffffu, nib, 1);
            nib = (lane & 1) ? (t | (nib << 4))  : (nib | (t << 4));
            t = __shfl_xor_sync(0xffffffffu, nib, 2);
            nib = (lane & 2) ? (t | (nib << 8))  : (nib | (t << 8));
            t = __shfl_xor_sync(0xffffffffu, nib, 4);
            nib = (lane & 4) ? (t | (nib << 16)) : (nib | (t << 16));
            if ((lane & 7) == 0)
                rowsW[r * RSTR + 4 * q + (lane >> 3)] = nib;
        }
    }
    if (threadIdx.x < NBINS) shist[threadIdx.x] = 0;
    __syncthreads();

    // ---- Phase B: triangles. One thread per node. ----
    int i = threadIdx.x;
    uint32_t my[WPR];
    int deg = 0;
    {
        const uint4* r4 = rows4[i];
#pragma unroll
        for (int k = 0; k < 4; ++k) {
            uint4 v = r4[k];
            my[4*k]   = v.x; my[4*k+1] = v.y; my[4*k+2] = v.z; my[4*k+3] = v.w;
            deg += __popc(v.x) + __popc(v.y) + __popc(v.z) + __popc(v.w);
        }
    }

    int tri = 0;
#pragma unroll
    for (int w = 0; w < WPR; ++w) {
        uint32_t m = my[w];
        while (m) {
            int j = (w << 5) + (__ffs(m) - 1);
            m &= m - 1;
            const uint4* rj = rows4[j];
            int c = 0;
#pragma unroll
            for (int k = 0; k < 4; ++k) {
                uint4 v = rj[k];                   // LDS.128
                c += __popc(my[4*k]   & v.x) + __popc(my[4*k+1] & v.y)
                   + __popc(my[4*k+2] & v.z) + __popc(my[4*k+3] & v.w);
            }
            tri += c;
        }
    }

    // ---- Phase C: bin (IEEE-exact vs JAX fp32) + histogram ----
    int bin = 0;
    if (deg >= 2) {
        float denom = (float)deg * (float)(deg - 1);
        float c  = __fdiv_rn((float)tri, denom);
        float cb = __fmul_rn(c, (float)NBINS);
        bin = (int)cb;
        bin = bin < 0 ? 0 : (bin > NBINS - 1 ? NBINS - 1 : bin);
    }
    atomicAdd(&shist[bin], 1);
    __syncthreads();

    if (threadIdx.x < NBINS)
        g_histf[s][b][threadIdx.x] = (float)shist[threadIdx.x];
}

// ---------------------------------------------------------------------------
// Kernel 2: RBF kernel sums + last-block finalize. grid=(8,3).
// Each block stages all 128 ys rows once (stride 101 -> conflict-free) and
// sweeps 16 i-rows. Last finishing block combines g_acc into out.
// ---------------------------------------------------------------------------
__global__ void mmd_kernel(float* __restrict__ out) {
    int m = blockIdx.y;          // 0: (h1,h1)  1: (h2,h2)  2: (h1,h2)
    int j = threadIdx.x;         // 128 threads

    const float* __restrict__ hx0 = &g_histf[(m == 1) ? 1 : 0][0][0];
    const float* __restrict__ hy0 = &g_histf[(m == 0) ? 0 : 1][0][0];

    __shared__ float xs[NBINS];
    __shared__ float ys[BATCH][NBINS + 1];   // stride 101

    for (int t = j; t < BATCH * NBINS; t += 128)
        ys[t / NBINS][t % NBINS] = hy0[t];
    __syncthreads();

    float acc = 0.0f;
    for (int ii = 0; ii < 16; ++ii) {
        int i = blockIdx.x * 16 + ii;
        if (j < NBINS) xs[j] = hx0[i * NBINS + j];
        __syncthreads();

        float d2 = 0.0f;
#pragma unroll 4
        for (int k = 0; k < NBINS; ++k) {
            float d = xs[k] - ys[j][k];
            d2 = fmaf(d, d, d2);
        }
        acc += expf(-0.5f * d2);
        __syncthreads();
    }

#pragma unroll
    for (int o = 16; o; o >>= 1)
        acc += __shfl_down_sync(0xffffffffu, acc, o);
    if ((j & 31) == 0)
        atomicAdd(&g_acc[m], acc);

    // last-block-out finalize (24 blocks total)
    __syncthreads();
    if (j == 0) {
        __threadfence();
        unsigned t = atomicAdd(&g_done, 1u);
        if (t == 23u) {
            __threadfence();
            const float inv = 1.0f / (128.0f * 128.0f);
            out[0] = (g_acc[0] + g_acc[1] - 2.0f * g_acc[2]) * inv;
            g_done = 0;                       // reset for graph replay
        }
    }
}

// ---------------------------------------------------------------------------
extern "C" void kernel_launch(void* const* d_in, const int* in_sizes, int n_in,
                              void* d_out, int out_size) {
    const float* a1 = (const float*)d_in[0];
    const float* a2 = (const float*)d_in[1];

    cluster_kernel<<<2 * BATCH, 512>>>(a1, a2);   // fused pack + triangles
    dim3 g(8, 3);
    mmd_kernel<<<g, 128>>>((float*)d_out);
}

// round 5
// speedup vs baseline: 1.2667x; 1.2667x over previous
#include <cuda_runtime.h>
#include <stdint.h>

// Problem constants (fixed by the reference)
#define BATCH 128
#define NN    512
#define NBINS 100
#define WPR   (NN / 32)   // 16 words per bitset row
#define RSTR  20          // padded row stride in words (80B, 16B-aligned)

// Scratch (allocation-free: __device__ globals)
__device__ float    g_histf[2][BATCH][NBINS];   // histograms (exact small ints)
__device__ float    g_acc[3];                   // Kxx, Kyy, Kxy sums
__device__ unsigned g_done = 0;                 // mmd completion ticket

// ---------------------------------------------------------------------------
// Kernel 1 (FUSED pack + cluster): one block per graph.
//  A: stream 1MB fp32 adjacency (float4 LDG.128), shfl-tree pack to smem bitset.
//  B: per-node triangle count, intersections via LDS.128.
//  C: block-local histogram -> direct global store (block owns its slot).
// ---------------------------------------------------------------------------
__global__ void __launch_bounds__(512) cluster_kernel(
        const float* __restrict__ a1, const float* __restrict__ a2) {
    int sb = blockIdx.x;          // 0..255
    int s  = sb >> 7;
    int b  = sb & (BATCH - 1);

    __shared__ uint4 rows4[NN][RSTR / 4];    // 512*80 = 40960 B, 16B aligned
    __shared__ int   shist[NBINS];
    uint32_t* rowsW = reinterpret_cast<uint32_t*>(rows4);

    int wid  = threadIdx.x >> 5;
    int lane = threadIdx.x & 31;

    if (sb == 0 && threadIdx.x < 3) g_acc[threadIdx.x] = 0.0f;  // stream-ordered

    // ---- Phase A: pack directly from global floats ----
    const float4* __restrict__ src =
        reinterpret_cast<const float4*>((s ? a2 : a1) + (size_t)b * NN * NN);

    for (int r = wid; r < NN; r += 16) {           // 32 rows per warp
        const float4* p = src + r * (NN / 4);      // 128 float4 per row
#pragma unroll
        for (int q = 0; q < 4; ++q) {
            float4 v = p[q * 32 + lane];           // contiguous per-warp
            uint32_t nib = (uint32_t)(v.x != 0.0f)
                         | ((uint32_t)(v.y != 0.0f) << 1)
                         | ((uint32_t)(v.z != 0.0f) << 2)
                         | ((uint32_t)(v.w != 0.0f) << 3);
            uint32_t t;
            t = __shfl_xor_sync(0xffffffffu, nib, 1);
            nib = (lane & 1) ? (t | (nib << 4))  : (nib | (t << 4));
            t = __shfl_xor_sync(0xffffffffu, nib, 2);
            nib = (lane & 2) ? (t | (nib << 8))  : (nib | (t << 8));
            t = __shfl_xor_sync(0xffffffffu, nib, 4);
            nib = (lane & 4) ? (t | (nib << 16)) : (nib | (t << 16));
            if ((lane & 7) == 0)
                rowsW[r * RSTR + 4 * q + (lane >> 3)] = nib;
        }
    }
    if (threadIdx.x < NBINS) shist[threadIdx.x] = 0;
    __syncthreads();

    // ---- Phase B: triangles. One thread per node. ----
    int i = threadIdx.x;
    uint32_t my[WPR];
    int deg = 0;
    {
        const uint4* r4 = rows4[i];
#pragma unroll
        for (int k = 0; k < 4; ++k) {
            uint4 v = r4[k];
            my[4*k]   = v.x; my[4*k+1] = v.y; my[4*k+2] = v.z; my[4*k+3] = v.w;
            deg += __popc(v.x) + __popc(v.y) + __popc(v.z) + __popc(v.w);
        }
    }

    int tri = 0;
#pragma unroll
    for (int w = 0; w < WPR; ++w) {
        uint32_t m = my[w];
        while (m) {
            int j = (w << 5) + (__ffs(m) - 1);
            m &= m - 1;
            const uint4* rj = rows4[j];
            int c = 0;
#pragma unroll
            for (int k = 0; k < 4; ++k) {
                uint4 v = rj[k];                   // LDS.128
                c += __popc(my[4*k]   & v.x) + __popc(my[4*k+1] & v.y)
                   + __popc(my[4*k+2] & v.z) + __popc(my[4*k+3] & v.w);
            }
            tri += c;
        }
    }

    // ---- Phase C: bin (IEEE-exact vs JAX fp32) + histogram ----
    int bin = 0;
    if (deg >= 2) {
        float denom = (float)deg * (float)(deg - 1);
        float c  = __fdiv_rn((float)tri, denom);
        float cb = __fmul_rn(c, (float)NBINS);
        bin = (int)cb;
        bin = bin < 0 ? 0 : (bin > NBINS - 1 ? NBINS - 1 : bin);
    }
    atomicAdd(&shist[bin], 1);
    __syncthreads();

    if (threadIdx.x < NBINS)
        g_histf[s][b][threadIdx.x] = (float)shist[threadIdx.x];
}

// ---------------------------------------------------------------------------
// Kernel 2: RBF kernel sums, one THREAD per (i,j) pair, 16x16 tiles.
// grid=(8,8,3): x=i-tile, y=j-tile, z=m. 256 threads: ti=tid/16, tj=tid%16.
// smem rows stride 101 -> ys[tj][k] hits 16 distinct banks (5*tj mod 32).
// Block smem-reduce -> 1 atomic; last block of 192 finalizes the scalar.
// ---------------------------------------------------------------------------
__global__ void __launch_bounds__(256) mmd_kernel(float* __restrict__ out) {
    int m  = blockIdx.z;         // 0: (h1,h1)  1: (h2,h2)  2: (h1,h2)
    int t  = threadIdx.x;
    int ti = t >> 4;
    int tj = t & 15;

    const float* __restrict__ hx0 = &g_histf[(m == 1) ? 1 : 0][0][0];
    const float* __restrict__ hy0 = &g_histf[(m == 0) ? 0 : 1][0][0];

    __shared__ float xs[16][NBINS + 1];   // stride 101
    __shared__ float ys[16][NBINS + 1];
    __shared__ float red[8];

    int i0 = blockIdx.x * 16;
    int j0 = blockIdx.y * 16;

    for (int e = t; e < 16 * NBINS; e += 256) {
        int r = e / NBINS, k = e % NBINS;
        xs[r][k] = hx0[(i0 + r) * NBINS + k];
        ys[r][k] = hy0[(j0 + r) * NBINS + k];
    }
    __syncthreads();

    float d2 = 0.0f;
#pragma unroll 4
    for (int k = 0; k < NBINS; ++k) {
        float d = xs[ti][k] - ys[tj][k];
        d2 = fmaf(d, d, d2);
    }
    float kv = expf(-0.5f * d2);

    // block reduce: warp shfl -> smem -> warp 0 -> single atomic
#pragma unroll
    for (int o = 16; o; o >>= 1)
        kv += __shfl_down_sync(0xffffffffu, kv, o);
    if ((t & 31) == 0) red[t >> 5] = kv;
    __syncthreads();
    if (t < 32) {
        float v = (t < 8) ? red[t] : 0.0f;
#pragma unroll
        for (int o = 4; o; o >>= 1)
            v += __shfl_down_sync(0xffffffffu, v, o);
        if (t == 0) atomicAdd(&g_acc[m], v);
    }

    // last-block-out finalize (8*8*3 = 192 blocks)
    __syncthreads();
    if (t == 0) {
        __threadfence();
        unsigned tk = atomicAdd(&g_done, 1u);
        if (tk == 191u) {
            __threadfence();
            const float inv = 1.0f / (128.0f * 128.0f);
            out[0] = (g_acc[0] + g_acc[1] - 2.0f * g_acc[2]) * inv;
            g_done = 0;                       // reset for graph replay
        }
    }
}

// ---------------------------------------------------------------------------
extern "C" void kernel_launch(void* const* d_in, const int* in_sizes, int n_in,
                              void* d_out, int out_size) {
    const float* a1 = (const float*)d_in[0];
    const float* a2 = (const float*)d_in[1];

    cluster_kernel<<<2 * BATCH, 512>>>(a1, a2);   // fused pack + triangles
    dim3 g(8, 8, 3);
    mmd_kernel<<<g, 256>>>((float*)d_out);
}

// round 6
// speedup vs baseline: 1.3632x; 1.0762x over previous
#include <cuda_runtime.h>
#include <stdint.h>

// Problem constants (fixed by the reference)
#define BATCH 128
#define NN    512
#define NBINS 100
#define WPR   (NN / 32)   // 16 words per bitset row
#define RSTR  20          // padded row stride in words (80B, 16B-aligned)

// Scratch (allocation-free: __device__ globals)
__device__ float    g_histf[2][BATCH][NBINS];   // histograms (exact small ints)
__device__ float    g_acc[3];                   // Kxx, Kyy, Kxy sums
__device__ unsigned g_done = 0;                 // mmd completion ticket

// ---------------------------------------------------------------------------
// Kernel 1 (FUSED pack + cluster): one block per graph.
//  A: stream 1MB fp32 adjacency (4-deep float4 LDG.128), pack via BALLOT into
//     a PERMUTED column layout (permutation-invariant for popc intersections):
//     word 4q+c of row r holds bit l  <=>  A[r][q*128 + 4*l + c] != 0.
//     No shfl chains: ballots are warp-uniform, one lane does STS.128.
//  B: per-node triangle count, intersections via LDS.128 (stride 20 words).
//     Neighbor decode inverts the permutation: j = (w>>2)*128 + 4*bit + (w&3).
//  C: block-local histogram -> direct global store (block owns its slot).
// ---------------------------------------------------------------------------
__global__ void __launch_bounds__(512) cluster_kernel(
        const float* __restrict__ a1, const float* __restrict__ a2) {
    int sb = blockIdx.x;          // 0..255
    int s  = sb >> 7;
    int b  = sb & (BATCH - 1);

    __shared__ uint4 rows4[NN][RSTR / 4];    // 512*80 = 40960 B, 16B aligned
    __shared__ int   shist[NBINS];

    int wid  = threadIdx.x >> 5;
    int lane = threadIdx.x & 31;

    if (sb == 0 && threadIdx.x < 3) g_acc[threadIdx.x] = 0.0f;  // stream-ordered

    // ---- Phase A: ballot pack, 4 loads in flight per thread ----
    const float4* __restrict__ src =
        reinterpret_cast<const float4*>((s ? a2 : a1) + (size_t)b * NN * NN);

    for (int r = wid; r < NN; r += 16) {           // 32 rows per warp
        const float4* p = src + r * (NN / 4);      // 128 float4 per row
        float4 v0 = p[lane];                       // MLP = 4
        float4 v1 = p[32 + lane];
        float4 v2 = p[64 + lane];
        float4 v3 = p[96 + lane];
#pragma unroll
        for (int q = 0; q < 4; ++q) {
            float4 v = (q == 0) ? v0 : (q == 1) ? v1 : (q == 2) ? v2 : v3;
            uint32_t bx = __ballot_sync(0xffffffffu, v.x != 0.0f);
            uint32_t by = __ballot_sync(0xffffffffu, v.y != 0.0f);
            uint32_t bz = __ballot_sync(0xffffffffu, v.z != 0.0f);
            uint32_t bw = __ballot_sync(0xffffffffu, v.w != 0.0f);
            if (lane == q)                         // ballots warp-uniform
                rows4[r][q] = make_uint4(bx, by, bz, bw);
        }
    }
    if (threadIdx.x < NBINS) shist[threadIdx.x] = 0;
    __syncthreads();

    // ---- Phase B: triangles. One thread per node. ----
    int i = threadIdx.x;
    uint32_t my[WPR];
    int deg = 0;
    {
        const uint4* r4 = rows4[i];
#pragma unroll
        for (int k = 0; k < 4; ++k) {
            uint4 v = r4[k];
            my[4*k]   = v.x; my[4*k+1] = v.y; my[4*k+2] = v.z; my[4*k+3] = v.w;
            deg += __popc(v.x) + __popc(v.y) + __popc(v.z) + __popc(v.w);
        }
    }

    int tri = 0;
#pragma unroll
    for (int w = 0; w < WPR; ++w) {
        uint32_t m = my[w];
        int base = (w >> 2) * 128 + (w & 3);       // permutation inverse
        while (m) {
            int l = __ffs(m) - 1;
            m &= m - 1;
            int j = base + 4 * l;                  // neighbor node id
            const uint4* rj = rows4[j];
            int c = 0;
#pragma unroll
            for (int k = 0; k < 4; ++k) {
                uint4 v = rj[k];                   // LDS.128
                c += __popc(my[4*k]   & v.x) + __popc(my[4*k+1] & v.y)
                   + __popc(my[4*k+2] & v.z) + __popc(my[4*k+3] & v.w);
            }
            tri += c;
        }
    }

    // ---- Phase C: bin (IEEE-exact vs JAX fp32) + histogram ----
    int bin = 0;
    if (deg >= 2) {
        float denom = (float)deg * (float)(deg - 1);
        float c  = __fdiv_rn((float)tri, denom);
        float cb = __fmul_rn(c, (float)NBINS);
        bin = (int)cb;
        bin = bin < 0 ? 0 : (bin > NBINS - 1 ? NBINS - 1 : bin);
    }
    atomicAdd(&shist[bin], 1);
    __syncthreads();

    if (threadIdx.x < NBINS)
        g_histf[s][b][threadIdx.x] = (float)shist[threadIdx.x];
}

// ---------------------------------------------------------------------------
// Kernel 2: RBF kernel sums, one THREAD per (i,j) pair, 16x16 tiles.
// grid=(8,8,3). smem stride 101 -> conflict-free. One atomic per block;
// last of 192 blocks finalizes the scalar.
// ---------------------------------------------------------------------------
__global__ void __launch_bounds__(256) mmd_kernel(float* __restrict__ out) {
    int m  = blockIdx.z;         // 0: (h1,h1)  1: (h2,h2)  2: (h1,h2)
    int t  = threadIdx.x;
    int ti = t >> 4;
    int tj = t & 15;

    const float* __restrict__ hx0 = &g_histf[(m == 1) ? 1 : 0][0][0];
    const float* __restrict__ hy0 = &g_histf[(m == 0) ? 0 : 1][0][0];

    __shared__ float xs[16][NBINS + 1];   // stride 101
    __shared__ float ys[16][NBINS + 1];
    __shared__ float red[8];

    int i0 = blockIdx.x * 16;
    int j0 = blockIdx.y * 16;

    for (int e = t; e < 16 * NBINS; e += 256) {
        int r = e / NBINS, k = e % NBINS;
        xs[r][k] = hx0[(i0 + r) * NBINS + k];
        ys[r][k] = hy0[(j0 + r) * NBINS + k];
    }
    __syncthreads();

    float d2 = 0.0f;
#pragma unroll 4
    for (int k = 0; k < NBINS; ++k) {
        float d = xs[ti][k] - ys[tj][k];
        d2 = fmaf(d, d, d2);
    }
    float kv = expf(-0.5f * d2);

#pragma unroll
    for (int o = 16; o; o >>= 1)
        kv += __shfl_down_sync(0xffffffffu, kv, o);
    if ((t & 31) == 0) red[t >> 5] = kv;
    __syncthreads();
    if (t < 32) {
        float v = (t < 8) ? red[t] : 0.0f;
#pragma unroll
        for (int o = 4; o; o >>= 1)
            v += __shfl_down_sync(0xffffffffu, v, o);
        if (t == 0) atomicAdd(&g_acc[m], v);
    }

    // last-block-out finalize (8*8*3 = 192 blocks)
    __syncthreads();
    if (t == 0) {
        __threadfence();
        unsigned tk = atomicAdd(&g_done, 1u);
        if (tk == 191u) {
            __threadfence();
            const float inv = 1.0f / (128.0f * 128.0f);
            out[0] = (g_acc[0] + g_acc[1] - 2.0f * g_acc[2]) * inv;
            g_done = 0;                       // reset for graph replay
        }
    }
}

// ---------------------------------------------------------------------------
extern "C" void kernel_launch(void* const* d_in, const int* in_sizes, int n_in,
                              void* d_out, int out_size) {
    const float* a1 = (const float*)d_in[0];
    const float* a2 = (const float*)d_in[1];

    cluster_kernel<<<2 * BATCH, 512>>>(a1, a2);   // fused pack + triangles
    dim3 g(8, 8, 3);
    mmd_kernel<<<g, 256>>>((float*)d_out);
}

// round 7
// speedup vs baseline: 1.6129x; 1.1831x over previous
#include <cuda_runtime.h>
#include <stdint.h>

// Problem constants (fixed by the reference)
#define BATCH 128
#define NN    512
#define NBINS 100
#define WPR   (NN / 32)   // 16 words per bitset row
#define RSTR  20          // padded row stride in words (80B, 16B-aligned)

// Scratch (allocation-free: __device__ globals)
__device__ float    g_histf[2][BATCH][NBINS];   // histograms (exact small ints)
__device__ float    g_acc[3];                   // Kxx, Kyy, Kxy sums
__device__ unsigned g_done = 0;                 // mmd completion ticket

// 32x32 bit-matrix transpose across a warp: out[l] bit k = in[k] bit l.
__device__ __forceinline__ uint32_t transpose32(uint32_t x, int lane) {
#pragma unroll
    for (int i = 16; i > 0; i >>= 1) {
        uint32_t m = (i == 16) ? 0xFFFF0000u : (i == 8) ? 0xFF00FF00u
                   : (i == 4)  ? 0xF0F0F0F0u : (i == 2) ? 0xCCCCCCCCu
                                             : 0xAAAAAAAAu;
        uint32_t y = __shfl_xor_sync(0xffffffffu, x, i);
        x = (lane & i) ? ((x & m) | ((y & m) >> i))
                       : ((x & ~m) | ((y & ~m) << i));
    }
    return x;
}

// ---------------------------------------------------------------------------
// Kernel 1 (FUSED pack + mirror + cluster): one block per graph.
//  A: symmetric input -> read ONLY column-panels q >= r>>7 per row (62.5% of
//     bytes). Ballot-pack into permuted layout: word 4q+c bit l <=> col
//     q*128+4l+c. Rows paired (k, 511-k) -> constant 5 panel-loads per iter.
//  M: mirror sub-diagonal panels via warp 32x32 bit transposes in smem.
//  B: per-node triangle count, intersections via LDS.128.
//  C: block-local histogram -> direct global store.
// ---------------------------------------------------------------------------
__global__ void __launch_bounds__(512) cluster_kernel(
        const float* __restrict__ a1, const float* __restrict__ a2) {
    int sb = blockIdx.x;          // 0..255
    int s  = sb >> 7;
    int b  = sb & (BATCH - 1);

    __shared__ uint4 rows4[NN][RSTR / 4];    // 512*80 = 40960 B
    __shared__ int   shist[NBINS];

    int wid  = threadIdx.x >> 5;
    int lane = threadIdx.x & 31;

    if (sb == 0 && threadIdx.x < 3) g_acc[threadIdx.x] = 0.0f;

    const float4* __restrict__ src =
        reinterpret_cast<const float4*>((s ? a2 : a1) + (size_t)b * NN * NN);

#define PACK_PANEL(vv, rr, qq) {                                          \
    uint32_t bx = __ballot_sync(0xffffffffu, (vv).x != 0.0f);             \
    uint32_t by = __ballot_sync(0xffffffffu, (vv).y != 0.0f);             \
    uint32_t bz = __ballot_sync(0xffffffffu, (vv).z != 0.0f);             \
    uint32_t bw = __ballot_sync(0xffffffffu, (vv).w != 0.0f);             \
    if (lane == 0) rows4[rr][qq] = make_uint4(bx, by, bz, bw); }

    // ---- Phase A: pack upper panels only, rows paired (t, 511-t) ----
    for (int t = wid; t < 256; t += 16) {
        int ra = t;              // needs panels (t>>7)..3   (4 or 3)
        int rb = 511 - t;        // needs panels (rb>>7)..3  (1 or 2)
        const float4* pa = src + ra * (NN / 4);
        const float4* pb = src + rb * (NN / 4);
        int qa0 = ra >> 7;       // 0 or 1  (warp-uniform)
        int qb0 = rb >> 7;       // 3 or 2  (warp-uniform)

        float4 va0, va1, va2, va3, vb2, vb3;     // 5 loads in flight
        if (qa0 == 0) va0 = pa[0 * 32 + lane];
        va1 = pa[1 * 32 + lane];
        va2 = pa[2 * 32 + lane];
        va3 = pa[3 * 32 + lane];
        if (qb0 == 2) vb2 = pb[2 * 32 + lane];
        vb3 = pb[3 * 32 + lane];

        if (qa0 == 0) PACK_PANEL(va0, ra, 0);
        PACK_PANEL(va1, ra, 1);
        PACK_PANEL(va2, ra, 2);
        PACK_PANEL(va3, ra, 3);
        if (qb0 == 2) PACK_PANEL(vb2, rb, 2);
        PACK_PANEL(vb3, rb, 3);
    }
    if (threadIdx.x < NBINS) shist[threadIdx.x] = 0;
    __syncthreads();

    // ---- Phase M: mirror lower panels (R,Q), Q<R, from upper (Q,R) ----
    if (wid < 6) {
        const int RT[6] = {1, 2, 2, 3, 3, 3};
        const int QT[6] = {0, 0, 1, 0, 1, 2};
        int R = RT[wid], Q = QT[wid];
        // source: rows 128Q+4*lane+c, word-quad R  (components = c_w)
        uint4 u0 = rows4[128 * Q + 4 * lane + 0][R];
        uint4 u1 = rows4[128 * Q + 4 * lane + 1][R];
        uint4 u2 = rows4[128 * Q + 4 * lane + 2][R];
        uint4 u3 = rows4[128 * Q + 4 * lane + 3][R];
        u0.x = transpose32(u0.x, lane); u0.y = transpose32(u0.y, lane);
        u0.z = transpose32(u0.z, lane); u0.w = transpose32(u0.w, lane);
        u1.x = transpose32(u1.x, lane); u1.y = transpose32(u1.y, lane);
        u1.z = transpose32(u1.z, lane); u1.w = transpose32(u1.w, lane);
        u2.x = transpose32(u2.x, lane); u2.y = transpose32(u2.y, lane);
        u2.z = transpose32(u2.z, lane); u2.w = transpose32(u2.w, lane);
        u3.x = transpose32(u3.x, lane); u3.y = transpose32(u3.y, lane);
        u3.z = transpose32(u3.z, lane); u3.w = transpose32(u3.w, lane);
        // target: rows 128R+4*lane+c_w, word-quad Q (components = c)
        rows4[128 * R + 4 * lane + 0][Q] = make_uint4(u0.x, u1.x, u2.x, u3.x);
        rows4[128 * R + 4 * lane + 1][Q] = make_uint4(u0.y, u1.y, u2.y, u3.y);
        rows4[128 * R + 4 * lane + 2][Q] = make_uint4(u0.z, u1.z, u2.z, u3.z);
        rows4[128 * R + 4 * lane + 3][Q] = make_uint4(u0.w, u1.w, u2.w, u3.w);
    }
    __syncthreads();

    // ---- Phase B: triangles. One thread per node. ----
    int i = threadIdx.x;
    uint32_t my[WPR];
    int deg = 0;
    {
        const uint4* r4 = rows4[i];
#pragma unroll
        for (int k = 0; k < 4; ++k) {
            uint4 v = r4[k];
            my[4*k]   = v.x; my[4*k+1] = v.y; my[4*k+2] = v.z; my[4*k+3] = v.w;
            deg += __popc(v.x) + __popc(v.y) + __popc(v.z) + __popc(v.w);
        }
    }

    int tri = 0;
#pragma unroll
    for (int w = 0; w < WPR; ++w) {
        uint32_t m = my[w];
        int base = (w >> 2) * 128 + (w & 3);       // permutation inverse
        while (m) {
            int l = __ffs(m) - 1;
            m &= m - 1;
            int j = base + 4 * l;                  // neighbor node id
            const uint4* rj = rows4[j];
            int c = 0;
#pragma unroll
            for (int k = 0; k < 4; ++k) {
                uint4 v = rj[k];                   // LDS.128
                c += __popc(my[4*k]   & v.x) + __popc(my[4*k+1] & v.y)
                   + __popc(my[4*k+2] & v.z) + __popc(my[4*k+3] & v.w);
            }
            tri += c;
        }
    }

    // ---- Phase C: bin (IEEE-exact vs JAX fp32) + histogram ----
    int bin = 0;
    if (deg >= 2) {
        float denom = (float)deg * (float)(deg - 1);
        float c  = __fdiv_rn((float)tri, denom);
        float cb = __fmul_rn(c, (float)NBINS);
        bin = (int)cb;
        bin = bin < 0 ? 0 : (bin > NBINS - 1 ? NBINS - 1 : bin);
    }
    atomicAdd(&shist[bin], 1);
    __syncthreads();

    if (threadIdx.x < NBINS)
        g_histf[s][b][threadIdx.x] = (float)shist[threadIdx.x];
}

// ---------------------------------------------------------------------------
// Kernel 2: RBF kernel sums, one THREAD per (i,j) pair, 16x16 tiles.
// grid=(8,8,3). smem stride 101 -> conflict-free. One atomic per block;
// last of 192 blocks finalizes the scalar.
// ---------------------------------------------------------------------------
__global__ void __launch_bounds__(256) mmd_kernel(float* __restrict__ out) {
    int m  = blockIdx.z;
    int t  = threadIdx.x;
    int ti = t >> 4;
    int tj = t & 15;

    const float* __restrict__ hx0 = &g_histf[(m == 1) ? 1 : 0][0][0];
    const float* __restrict__ hy0 = &g_histf[(m == 0) ? 0 : 1][0][0];

    __shared__ float xs[16][NBINS + 1];
    __shared__ float ys[16][NBINS + 1];
    __shared__ float red[8];

    int i0 = blockIdx.x * 16;
    int j0 = blockIdx.y * 16;

    for (int e = t; e < 16 * NBINS; e += 256) {
        int r = e / NBINS, k = e % NBINS;
        xs[r][k] = hx0[(i0 + r) * NBINS + k];
        ys[r][k] = hy0[(j0 + r) * NBINS + k];
    }
    __syncthreads();

    float d2 = 0.0f;
#pragma unroll 4
    for (int k = 0; k < NBINS; ++k) {
        float d = xs[ti][k] - ys[tj][k];
        d2 = fmaf(d, d, d2);
    }
    float kv = expf(-0.5f * d2);

#pragma unroll
    for (int o = 16; o; o >>= 1)
        kv += __shfl_down_sync(0xffffffffu, kv, o);
    if ((t & 31) == 0) red[t >> 5] = kv;
    __syncthreads();
    if (t < 32) {
        float v = (t < 8) ? red[t] : 0.0f;
#pragma unroll
        for (int o = 4; o; o >>= 1)
            v += __shfl_down_sync(0xffffffffu, v, o);
        if (t == 0) atomicAdd(&g_acc[m], v);
    }

    __syncthreads();
    if (t == 0) {
        __threadfence();
        unsigned tk = atomicAdd(&g_done, 1u);
        if (tk == 191u) {
            __threadfence();
            const float inv = 1.0f / (128.0f * 128.0f);
            out[0] = (g_acc[0] + g_acc[1] - 2.0f * g_acc[2]) * inv;
            g_done = 0;                       // reset for graph replay
        }
    }
}

// ---------------------------------------------------------------------------
extern "C" void kernel_launch(void* const* d_in, const int* in_sizes, int n_in,
                              void* d_out, int out_size) {
    const float* a1 = (const float*)d_in[0];
    const float* a2 = (const float*)d_in[1];

    cluster_kernel<<<2 * BATCH, 512>>>(a1, a2);   // pack + mirror + triangles
    dim3 g(8, 8, 3);
    mmd_kernel<<<g, 256>>>((float*)d_out);
}